// round 2
// baseline (speedup 1.0000x reference)
#include <cuda_runtime.h>

#define NN 100000
#define DD 128
#define CC 47
#define KK 256      // concat K = 2*D
#define TR 64       // rows per GEMM block
#define WPAD 132    // padded smem row for W (avoid conflicts, keep 16B align)
#define APAD 68     // padded smem row for A

// ---------------- scratch (static device allocations; no cudaMalloc) --------
__device__ __align__(128) float g_msg[(size_t)NN * DD];
__device__ __align__(128) float g_h[(size_t)NN * DD];
__device__ __align__(128) float g_xA[(size_t)NN * DD];
__device__ __align__(128) float g_xB[(size_t)NN * DD];
__device__ __align__(128) float g_cnt[NN];
__device__ __align__(128) float g_inv[NN];
__device__ __align__(128) float g_sum[DD];
__device__ __align__(128) float g_sum2[DD];
__device__ __align__(128) float g_scale[DD];
__device__ __align__(128) float g_shift[DD];

// ---------------- degree count + reciprocal ---------------------------------
__global__ void count_kernel(const int* __restrict__ dst, int E) {
    int e = blockIdx.x * blockDim.x + threadIdx.x;
    if (e < E) atomicAdd(&g_cnt[__ldg(dst + e)], 1.0f);
}

__global__ void inv_kernel() {
    int n = blockIdx.x * blockDim.x + threadIdx.x;
    if (n < NN) g_inv[n] = 1.0f / fmaxf(g_cnt[n], 1.0f);
}

// ---------------- edge scatter: one warp per edge, float4 per lane ----------
__global__ void scatter_kernel(const float4* __restrict__ x4,
                               const int* __restrict__ src,
                               const int* __restrict__ dst, int E) {
    int warp = (blockIdx.x * blockDim.x + threadIdx.x) >> 5;
    int lane = threadIdx.x & 31;
    if (warp >= E) return;
    int s = __ldg(src + warp);
    int d = __ldg(dst + warp);
    float4 v = __ldg(x4 + (size_t)s * 32 + lane);
    float* p = g_msg + (size_t)d * DD + lane * 4;
    asm volatile("red.global.add.v4.f32 [%0], {%1,%2,%3,%4};"
                 :: "l"(p), "f"(v.x), "f"(v.y), "f"(v.z), "f"(v.w)
                 : "memory");
}

// ---------------- fused SAGE GEMM: h = [x | msg*inv] @ [Wl;Wr]^T + bl -------
// Also accumulates per-column sum / sum^2 for BatchNorm into g_sum / g_sum2.
__global__ __launch_bounds__(256, 1) void gemm_kernel(
    const float4* __restrict__ x4,
    const float* __restrict__ Wl,
    const float* __restrict__ Wr,
    const float4* __restrict__ bl4) {
    extern __shared__ float sm[];
    float* Ws    = sm;                    // KK * WPAD
    float* As    = Ws + KK * WPAD;        // KK * APAD
    float* ssum  = As + KK * APAD;        // DD
    float* ssum2 = ssum + DD;             // DD

    int tid  = threadIdx.x;
    int row0 = blockIdx.x * TR;

    if (tid < DD) { ssum[tid] = 0.f; ssum2[tid] = 0.f; }

    // load both weight matrices transposed: Ws[k][j] = W[j][k]
    for (int idx = tid; idx < DD * DD; idx += 256) {
        int j = idx >> 7, k = idx & 127;
        Ws[k * WPAD + j]        = __ldg(Wl + idx);
        Ws[(k + DD) * WPAD + j] = __ldg(Wr + idx);
    }

    // load A tile transposed: As[k][r] ; k<128 -> x, k>=128 -> msg*inv
    const float4* msg4 = (const float4*)g_msg;
    for (int idx = tid; idx < TR * 64; idx += 256) {
        int r = idx >> 6, k4 = idx & 63;
        int row = row0 + r;
        float4 v = make_float4(0.f, 0.f, 0.f, 0.f);
        if (row < NN) {
            if (k4 < 32) {
                v = __ldg(x4 + (size_t)row * 32 + k4);
            } else {
                v = msg4[(size_t)row * 32 + (k4 - 32)];
                float iv = g_inv[row];
                v.x *= iv; v.y *= iv; v.z *= iv; v.w *= iv;
            }
        }
        float* a = &As[(k4 * 4) * APAD + r];
        a[0]        = v.x;
        a[APAD]     = v.y;
        a[2 * APAD] = v.z;
        a[3 * APAD] = v.w;
    }
    __syncthreads();

    int lane = tid & 31, wid = tid >> 5;
    int r0 = wid * 8;     // 8 warps * 8 rows = 64
    int c0 = lane * 4;    // 32 lanes * 4 cols = 128

    float acc[8][4];
#pragma unroll
    for (int i = 0; i < 8; i++)
#pragma unroll
        for (int j = 0; j < 4; j++) acc[i][j] = 0.f;

    const float* wsb = Ws + c0;
    const float* asb = As + r0;

#pragma unroll 4
    for (int k = 0; k < KK; k++) {
        float4 w  = *(const float4*)(wsb + k * WPAD);
        float4 a0 = *(const float4*)(asb + k * APAD);
        float4 a1 = *(const float4*)(asb + k * APAD + 4);
        float ar[8] = {a0.x, a0.y, a0.z, a0.w, a1.x, a1.y, a1.z, a1.w};
#pragma unroll
        for (int i = 0; i < 8; i++) {
            acc[i][0] += ar[i] * w.x;
            acc[i][1] += ar[i] * w.y;
            acc[i][2] += ar[i] * w.z;
            acc[i][3] += ar[i] * w.w;
        }
    }

    float4 bb = __ldg(bl4 + lane);
    float4* h4 = (float4*)g_h;
    float psum[4]  = {0.f, 0.f, 0.f, 0.f};
    float psum2[4] = {0.f, 0.f, 0.f, 0.f};
#pragma unroll
    for (int i = 0; i < 8; i++) {
        int row = row0 + r0 + i;
        if (row < NN) {
            float4 hv;
            hv.x = acc[i][0] + bb.x;
            hv.y = acc[i][1] + bb.y;
            hv.z = acc[i][2] + bb.z;
            hv.w = acc[i][3] + bb.w;
            h4[(size_t)row * 32 + lane] = hv;
            psum[0] += hv.x; psum[1] += hv.y; psum[2] += hv.z; psum[3] += hv.w;
            psum2[0] += hv.x * hv.x; psum2[1] += hv.y * hv.y;
            psum2[2] += hv.z * hv.z; psum2[3] += hv.w * hv.w;
        }
    }
#pragma unroll
    for (int j = 0; j < 4; j++) {
        atomicAdd(&ssum[c0 + j],  psum[j]);
        atomicAdd(&ssum2[c0 + j], psum2[j]);
    }
    __syncthreads();
    if (tid < DD) {
        atomicAdd(&g_sum[tid],  ssum[tid]);
        atomicAdd(&g_sum2[tid], ssum2[tid]);
    }
}

// ---------------- BN scale/shift precompute ---------------------------------
__global__ void bnprep_kernel(const float* __restrict__ gamma,
                              const float* __restrict__ beta) {
    int c = threadIdx.x;
    float invN = 1.0f / (float)NN;
    float mu  = g_sum[c] * invN;
    float var = g_sum2[c] * invN - mu * mu;
    float rs  = rsqrtf(var + 1e-5f);
    float a   = gamma[c] * rs;
    g_scale[c] = a;
    g_shift[c] = beta[c] - mu * a;
}

// ---------------- BN apply + ReLU + residual --------------------------------
__global__ void bnfin_kernel(const float4* __restrict__ xin4,
                             float4* __restrict__ xout4) {
    int i = blockIdx.x * blockDim.x + threadIdx.x;
    if (i >= NN * 32) return;
    int c4 = i & 31;
    float4 hv = ((const float4*)g_h)[i];
    float4 sc = ((const float4*)g_scale)[c4];
    float4 sh = ((const float4*)g_shift)[c4];
    float4 xv = __ldg(xin4 + i);
    float4 o;
    o.x = xv.x + fmaxf(0.f, hv.x * sc.x + sh.x);
    o.y = xv.y + fmaxf(0.f, hv.y * sc.y + sh.y);
    o.z = xv.z + fmaxf(0.f, hv.z * sc.z + sh.z);
    o.w = xv.w + fmaxf(0.f, hv.w * sc.w + sh.w);
    xout4[i] = o;
}

// ---------------- final linear: out = x @ lin_W^T + lin_b -------------------
__global__ __launch_bounds__(256) void final_kernel(
    const float4* __restrict__ x4,
    const float4* __restrict__ W4,
    const float* __restrict__ bias,
    float* __restrict__ out) {
    extern __shared__ float sm[];
    float4* Xs = (float4*)sm;        // 128 rows * 32 float4
    float4* Ws = Xs + 128 * 32;      // 47 rows  * 32 float4
    int tid  = threadIdx.x;
    int row0 = blockIdx.x * 128;

    for (int idx = tid; idx < 128 * 32; idx += 256) {
        int r = idx >> 5, k4 = idx & 31;
        int row = row0 + r;
        Xs[idx] = (row < NN) ? __ldg(x4 + (size_t)row * 32 + k4)
                             : make_float4(0.f, 0.f, 0.f, 0.f);
    }
    for (int idx = tid; idx < CC * 32; idx += 256) Ws[idx] = __ldg(W4 + idx);
    __syncthreads();

    for (int o = tid; o < 128 * CC; o += 256) {
        int r = o / CC, c = o - r * CC;
        int row = row0 + r;
        if (row >= NN) continue;
        float acc = 0.f;
#pragma unroll
        for (int k4 = 0; k4 < 32; k4++) {
            float4 a = Xs[r * 32 + k4];
            float4 w = Ws[c * 32 + k4];
            acc += a.x * w.x + a.y * w.y + a.z * w.z + a.w * w.w;
        }
        out[(size_t)row * CC + c] = acc + __ldg(bias + c);
    }
}

// ---------------- host orchestration ----------------------------------------
extern "C" void kernel_launch(void* const* d_in, const int* in_sizes, int n_in,
                              void* d_out, int out_size) {
    const float* x  = (const float*)d_in[0];
    const int*   ei = (const int*)d_in[1];
    int E = in_sizes[1] / 2;
    const int* src = ei;
    const int* dst = ei + E;

    void *msg_p, *cnt_p, *sum_p, *sum2_p, *xA_p, *xB_p;
    cudaGetSymbolAddress(&msg_p,  g_msg);
    cudaGetSymbolAddress(&cnt_p,  g_cnt);
    cudaGetSymbolAddress(&sum_p,  g_sum);
    cudaGetSymbolAddress(&sum2_p, g_sum2);
    cudaGetSymbolAddress(&xA_p,   g_xA);
    cudaGetSymbolAddress(&xB_p,   g_xB);

    const int SMEM_GEMM  = (KK * WPAD + KK * APAD + 2 * DD) * (int)sizeof(float);
    const int SMEM_FINAL = (128 * 32 + CC * 32) * (int)sizeof(float4);
    cudaFuncSetAttribute(gemm_kernel,  cudaFuncAttributeMaxDynamicSharedMemorySize, SMEM_GEMM);
    cudaFuncSetAttribute(final_kernel, cudaFuncAttributeMaxDynamicSharedMemorySize, SMEM_FINAL);

    // degree counts (shared by all 3 layers)
    cudaMemsetAsync(cnt_p, 0, NN * sizeof(float), 0);
    count_kernel<<<(E + 255) / 256, 256>>>(dst, E);
    inv_kernel<<<(NN + 255) / 256, 256>>>();

    const float* xin = x;
    float* xbufs[2] = {(float*)xA_p, (float*)xB_p};

    for (int L = 0; L < 3; L++) {
        const float* Wl = (const float*)d_in[2 + 5 * L];
        const float* bl = (const float*)d_in[3 + 5 * L];
        const float* Wr = (const float*)d_in[4 + 5 * L];
        const float* bg = (const float*)d_in[5 + 5 * L];
        const float* bb = (const float*)d_in[6 + 5 * L];
        float* xout = xbufs[L & 1];

        cudaMemsetAsync(msg_p, 0, (size_t)NN * DD * sizeof(float), 0);
        cudaMemsetAsync(sum_p, 0, DD * sizeof(float), 0);
        cudaMemsetAsync(sum2_p, 0, DD * sizeof(float), 0);

        scatter_kernel<<<(E * 32 + 255) / 256, 256>>>((const float4*)xin, src, dst, E);
        gemm_kernel<<<(NN + TR - 1) / TR, 256, SMEM_GEMM>>>(
            (const float4*)xin, Wl, Wr, (const float4*)bl);
        bnprep_kernel<<<1, DD>>>(bg, bb);
        bnfin_kernel<<<(NN * 32 + 255) / 256, 256>>>(
            (const float4*)xin, (float4*)xout);
        xin = xout;
    }

    final_kernel<<<(NN + 127) / 128, 256, SMEM_FINAL>>>(
        (const float4*)xin, (const float4*)d_in[17],
        (const float*)d_in[18], (float*)d_out);
}

// round 3
// speedup vs baseline: 1.3757x; 1.3757x over previous
#include <cuda_runtime.h>

#define NN 100000
#define DD 128
#define CC 47
#define EMAX 1700000
#define BM 128
#define BK 32
#define NBLK_SCAN 98   // ceil(100000/1024)

// ---------------- scratch (static; no cudaMalloc) ---------------------------
__device__ __align__(128) float g_msg[(size_t)NN * DD];
__device__ __align__(128) float g_h[(size_t)NN * DD];
__device__ __align__(128) float g_xA[(size_t)NN * DD];
__device__ __align__(128) float g_xB[(size_t)NN * DD];
__device__ __align__(128) float g_sum[DD];
__device__ __align__(128) float g_sum2[DD];
__device__ __align__(128) float g_scale[DD];
__device__ __align__(128) float g_shift[DD];
__device__ __align__(128) int   g_deg[NN];
__device__ __align__(128) int   g_scan[NN];
__device__ __align__(128) int   g_rowptr[NN];
__device__ __align__(128) int   g_cursor[NN];
__device__ __align__(128) int   g_srcs[EMAX];
__device__ __align__(128) int   g_bsum[128];
__device__ __align__(128) int   g_boff[128];

// ---------------- CSR build --------------------------------------------------
__global__ void deg_kernel(const int* __restrict__ dst, int E) {
    int e = blockIdx.x * blockDim.x + threadIdx.x;
    if (e < E) atomicAdd(&g_deg[__ldg(dst + e)], 1);
}

__global__ void scan1_kernel() {              // grid NBLK_SCAN, block 1024
    __shared__ int sm[1024];
    int i = blockIdx.x * 1024 + threadIdx.x;
    int v = (i < NN) ? g_deg[i] : 0;
    sm[threadIdx.x] = v;
    __syncthreads();
    for (int off = 1; off < 1024; off <<= 1) {
        int t = (threadIdx.x >= off) ? sm[threadIdx.x - off] : 0;
        __syncthreads();
        sm[threadIdx.x] += t;
        __syncthreads();
    }
    if (i < NN) g_scan[i] = sm[threadIdx.x];
    if (threadIdx.x == 1023) g_bsum[blockIdx.x] = sm[1023];
}

__global__ void scan2_kernel() {              // 1 thread
    int run = 0;
    for (int b = 0; b < NBLK_SCAN; b++) { g_boff[b] = run; run += g_bsum[b]; }
}

__global__ void scan3_kernel() {
    int i = blockIdx.x * blockDim.x + threadIdx.x;
    if (i >= NN) return;
    int r = g_boff[i >> 10] + g_scan[i] - g_deg[i];  // exclusive
    g_rowptr[i] = r;
    g_cursor[i] = r;
}

__global__ void fill_kernel(const int* __restrict__ src,
                            const int* __restrict__ dst, int E) {
    int e = blockIdx.x * blockDim.x + threadIdx.x;
    if (e >= E) return;
    int d = __ldg(dst + e);
    int pos = atomicAdd(&g_cursor[d], 1);
    g_srcs[pos] = __ldg(src + e);
}

// ---------------- gather-mean: one warp per node -----------------------------
__global__ void gather_kernel(const float4* __restrict__ x4) {
    int node = (blockIdx.x * blockDim.x + threadIdx.x) >> 5;
    int lane = threadIdx.x & 31;
    if (node >= NN) return;
    int start = g_rowptr[node];
    int deg   = g_deg[node];
    float4 acc = make_float4(0.f, 0.f, 0.f, 0.f);
    for (int i = 0; i < deg; i++) {
        int s = __ldg(&g_srcs[start + i]);
        float4 v = __ldg(x4 + (size_t)s * 32 + lane);
        acc.x += v.x; acc.y += v.y; acc.z += v.z; acc.w += v.w;
    }
    float iv = 1.f / fmaxf((float)deg, 1.f);
    acc.x *= iv; acc.y *= iv; acc.z *= iv; acc.w *= iv;
    ((float4*)g_msg)[(size_t)node * 32 + lane] = acc;
}

// ---------------- fused SAGE GEMM: h = [x | mean] @ [Wl;Wr]^T + bl ----------
// 128x128 tile, BK=32 chunks, 8x8 per-thread tile, BN sums in epilogue.
__global__ __launch_bounds__(256, 2) void gemm2_kernel(
    const float4* __restrict__ x4,
    const float*  __restrict__ Wl,
    const float*  __restrict__ Wr,
    const float*  __restrict__ bl) {
    __shared__ float As[BK * BM];
    __shared__ float Ws[BK * DD];
    __shared__ float ssum[DD], ssum2[DD];

    int tid  = threadIdx.x;
    int row0 = blockIdx.x * BM;
    if (tid < DD) { ssum[tid] = 0.f; ssum2[tid] = 0.f; }

    int lane = tid & 31, wid = tid >> 5;
    int tr = (wid >> 1) * 32 + (lane >> 3) * 8;   // thread row base (0..120)
    int tc = (wid & 1) * 64 + (lane & 7) * 8;     // thread col base (0..120)

    float acc[8][8];
#pragma unroll
    for (int i = 0; i < 8; i++)
#pragma unroll
        for (int j = 0; j < 8; j++) acc[i][j] = 0.f;

    const float4* msg4 = (const float4*)g_msg;

    for (int kc = 0; kc < 8; kc++) {
        // A chunk: 128 rows x 32 k (transposed into As[k][row])
#pragma unroll
        for (int l = 0; l < 4; l++) {
            int idx = tid + l * 256;        // 0..1023
            int row = idx & 127;
            int j   = idx >> 7;             // 0..7
            int grow = row0 + row;
            float4 v = make_float4(0.f, 0.f, 0.f, 0.f);
            if (grow < NN) {
                if (kc < 4) v = __ldg(x4   + (size_t)grow * 32 + kc * 8 + j);
                else        v = msg4[(size_t)grow * 32 + (kc - 4) * 8 + j];
            }
            int kb = j * 4;
            As[(kb + 0) * BM + row] = v.x;
            As[(kb + 1) * BM + row] = v.y;
            As[(kb + 2) * BM + row] = v.z;
            As[(kb + 3) * BM + row] = v.w;
        }
        // W chunk: 128 cols x 32 k (transposed into Ws[k][col])
        const float4* Wg = (kc < 4) ? (const float4*)Wl : (const float4*)Wr;
        int kk = (kc & 3) * 8;
#pragma unroll
        for (int l = 0; l < 4; l++) {
            int idx = tid + l * 256;
            int c = idx & 127;
            int j = idx >> 7;
            float4 v = __ldg(Wg + c * 32 + kk + j);
            int kb = j * 4;
            Ws[(kb + 0) * DD + c] = v.x;
            Ws[(kb + 1) * DD + c] = v.y;
            Ws[(kb + 2) * DD + c] = v.z;
            Ws[(kb + 3) * DD + c] = v.w;
        }
        __syncthreads();

#pragma unroll 8
        for (int k = 0; k < BK; k++) {
            float4 a0 = *(const float4*)&As[k * BM + tr];
            float4 a1 = *(const float4*)&As[k * BM + tr + 4];
            float4 w0 = *(const float4*)&Ws[k * DD + tc];
            float4 w1 = *(const float4*)&Ws[k * DD + tc + 4];
            float ar[8] = {a0.x, a0.y, a0.z, a0.w, a1.x, a1.y, a1.z, a1.w};
            float wv[8] = {w0.x, w0.y, w0.z, w0.w, w1.x, w1.y, w1.z, w1.w};
#pragma unroll
            for (int i = 0; i < 8; i++)
#pragma unroll
                for (int j = 0; j < 8; j++) acc[i][j] += ar[i] * wv[j];
        }
        __syncthreads();
    }

    // epilogue: bias, store h, BN partial sums
    float bcol[8];
#pragma unroll
    for (int j = 0; j < 8; j++) bcol[j] = __ldg(bl + tc + j);

    float psum[8], psum2[8];
#pragma unroll
    for (int j = 0; j < 8; j++) { psum[j] = 0.f; psum2[j] = 0.f; }

#pragma unroll
    for (int i = 0; i < 8; i++) {
        int grow = row0 + tr + i;
        if (grow < NN) {
            float hv[8];
#pragma unroll
            for (int j = 0; j < 8; j++) {
                hv[j] = acc[i][j] + bcol[j];
                psum[j]  += hv[j];
                psum2[j] += hv[j] * hv[j];
            }
            float4* dst0 = (float4*)(g_h + (size_t)grow * DD + tc);
            dst0[0] = make_float4(hv[0], hv[1], hv[2], hv[3]);
            dst0[1] = make_float4(hv[4], hv[5], hv[6], hv[7]);
        }
    }
#pragma unroll
    for (int j = 0; j < 8; j++) {
        atomicAdd(&ssum[tc + j],  psum[j]);
        atomicAdd(&ssum2[tc + j], psum2[j]);
    }
    __syncthreads();
    if (tid < DD) {
        atomicAdd(&g_sum[tid],  ssum[tid]);
        atomicAdd(&g_sum2[tid], ssum2[tid]);
    }
}

// ---------------- BN scale/shift precompute ---------------------------------
__global__ void bnprep_kernel(const float* __restrict__ gamma,
                              const float* __restrict__ beta) {
    int c = threadIdx.x;
    float invN = 1.0f / (float)NN;
    float mu  = g_sum[c] * invN;
    float var = g_sum2[c] * invN - mu * mu;
    float rs  = rsqrtf(var + 1e-5f);
    float a   = gamma[c] * rs;
    g_scale[c] = a;
    g_shift[c] = beta[c] - mu * a;
}

// ---------------- BN apply + ReLU + residual --------------------------------
__global__ void bnfin_kernel(const float4* __restrict__ xin4,
                             float4* __restrict__ xout4) {
    int i = blockIdx.x * blockDim.x + threadIdx.x;
    if (i >= NN * 32) return;
    int c4 = i & 31;
    float4 hv = ((const float4*)g_h)[i];
    float4 sc = ((const float4*)g_scale)[c4];
    float4 sh = ((const float4*)g_shift)[c4];
    float4 xv = __ldg(xin4 + i);
    float4 o;
    o.x = xv.x + fmaxf(0.f, hv.x * sc.x + sh.x);
    o.y = xv.y + fmaxf(0.f, hv.y * sc.y + sh.y);
    o.z = xv.z + fmaxf(0.f, hv.z * sc.z + sh.z);
    o.w = xv.w + fmaxf(0.f, hv.w * sc.w + sh.w);
    xout4[i] = o;
}

// ---------------- final linear: out = x @ lin_W^T + lin_b -------------------
__global__ __launch_bounds__(256) void final_kernel(
    const float4* __restrict__ x4,
    const float4* __restrict__ W4,
    const float* __restrict__ bias,
    float* __restrict__ out) {
    extern __shared__ float sm[];
    float4* Xs = (float4*)sm;        // 128 rows * 32 float4
    float4* Wk = Xs + 128 * 32;      // 47 rows  * 32 float4
    int tid  = threadIdx.x;
    int row0 = blockIdx.x * 128;

    for (int idx = tid; idx < 128 * 32; idx += 256) {
        int r = idx >> 5, k4 = idx & 31;
        int row = row0 + r;
        Xs[idx] = (row < NN) ? __ldg(x4 + (size_t)row * 32 + k4)
                             : make_float4(0.f, 0.f, 0.f, 0.f);
    }
    for (int idx = tid; idx < CC * 32; idx += 256) Wk[idx] = __ldg(W4 + idx);
    __syncthreads();

    for (int o = tid; o < 128 * CC; o += 256) {
        int r = o / CC, c = o - r * CC;
        int row = row0 + r;
        if (row >= NN) continue;
        float acc = 0.f;
#pragma unroll
        for (int k4 = 0; k4 < 32; k4++) {
            float4 a = Xs[r * 32 + k4];
            float4 w = Wk[c * 32 + k4];
            acc += a.x * w.x + a.y * w.y + a.z * w.z + a.w * w.w;
        }
        out[(size_t)row * CC + c] = acc + __ldg(bias + c);
    }
}

// ---------------- host orchestration ----------------------------------------
extern "C" void kernel_launch(void* const* d_in, const int* in_sizes, int n_in,
                              void* d_out, int out_size) {
    const float* x  = (const float*)d_in[0];
    const int*   ei = (const int*)d_in[1];
    int E = in_sizes[1] / 2;
    const int* src = ei;
    const int* dst = ei + E;

    void *deg_p, *sum_p, *sum2_p, *xA_p, *xB_p;
    cudaGetSymbolAddress(&deg_p,  g_deg);
    cudaGetSymbolAddress(&sum_p,  g_sum);
    cudaGetSymbolAddress(&sum2_p, g_sum2);
    cudaGetSymbolAddress(&xA_p,   g_xA);
    cudaGetSymbolAddress(&xB_p,   g_xB);

    const int SMEM_FINAL = (128 * 32 + CC * 32) * (int)sizeof(float4);
    cudaFuncSetAttribute(final_kernel, cudaFuncAttributeMaxDynamicSharedMemorySize, SMEM_FINAL);

    // ---- CSR build (once per launch) ----
    cudaMemsetAsync(deg_p, 0, NN * sizeof(int), 0);
    deg_kernel<<<(E + 255) / 256, 256>>>(dst, E);
    scan1_kernel<<<NBLK_SCAN, 1024>>>();
    scan2_kernel<<<1, 1>>>();
    scan3_kernel<<<(NN + 255) / 256, 256>>>();
    fill_kernel<<<(E + 255) / 256, 256>>>(src, dst, E);

    const float* xin = x;
    float* xbufs[2] = {(float*)xA_p, (float*)xB_p};

    for (int L = 0; L < 3; L++) {
        const float* Wl = (const float*)d_in[2 + 5 * L];
        const float* bl = (const float*)d_in[3 + 5 * L];
        const float* Wr = (const float*)d_in[4 + 5 * L];
        const float* bg = (const float*)d_in[5 + 5 * L];
        const float* bb = (const float*)d_in[6 + 5 * L];
        float* xout = xbufs[L & 1];

        cudaMemsetAsync(sum_p, 0, DD * sizeof(float), 0);
        cudaMemsetAsync(sum2_p, 0, DD * sizeof(float), 0);

        gather_kernel<<<(NN * 32 + 255) / 256, 256>>>((const float4*)xin);
        gemm2_kernel<<<(NN + BM - 1) / BM, 256>>>(
            (const float4*)xin, Wl, Wr, bl);
        bnprep_kernel<<<1, DD>>>(bg, bb);
        bnfin_kernel<<<(NN * 32 + 255) / 256, 256>>>(
            (const float4*)xin, (float4*)xout);
        xin = xout;
    }

    final_kernel<<<(NN + 127) / 128, 256, SMEM_FINAL>>>(
        (const float4*)xin, (const float4*)d_in[17],
        (const float*)d_in[18], (float*)d_out);
}

// round 6
// speedup vs baseline: 1.6319x; 1.1862x over previous
#include <cuda_runtime.h>
#include <cuda_bf16.h>
#include <cstdint>

#define NN 100000
#define DD 128
#define CC 47
#define EMAX 1700000
#define NBLK_SCAN 98

// ---------------- scratch ----------------------------------------------------
__device__ __align__(128) float g_h[(size_t)NN * DD];
__device__ __align__(128) float g_xA[(size_t)NN * DD];
__device__ __align__(128) float g_xB[(size_t)NN * DD];
__device__ __align__(128) __nv_bfloat16 g_xhi[(size_t)NN * DD];
__device__ __align__(128) __nv_bfloat16 g_xlo[(size_t)NN * DD];
__device__ __align__(128) __nv_bfloat16 g_mhi[(size_t)NN * DD];
__device__ __align__(128) __nv_bfloat16 g_mlo[(size_t)NN * DD];
__device__ __align__(128) __nv_bfloat16 g_whi[2 * DD * DD];
__device__ __align__(128) __nv_bfloat16 g_wlo[2 * DD * DD];
__device__ __align__(128) float g_sum[DD];
__device__ __align__(128) float g_sum2[DD];
__device__ __align__(128) float g_scale[DD];
__device__ __align__(128) float g_shift[DD];
__device__ __align__(128) int   g_deg[NN];
__device__ __align__(128) int   g_scan[NN];
__device__ __align__(128) int   g_rowptr[NN];
__device__ __align__(128) int   g_cursor[NN];
__device__ __align__(128) int   g_srcs[EMAX];
__device__ __align__(128) int   g_bsum[128];
__device__ __align__(128) int   g_boff[128];

__device__ __forceinline__ void split_bf16(float v, __nv_bfloat16& hi, __nv_bfloat16& lo) {
    hi = __float2bfloat16(v);
    lo = __float2bfloat16(v - __bfloat162float(hi));
}

__device__ __forceinline__ uint32_t smem_to_u32(const void* p) {
    uint32_t a;
    asm("{ .reg .u64 t; cvta.to.shared.u64 t, %1; cvt.u32.u64 %0, t; }"
        : "=r"(a) : "l"(p));
    return a;
}

__device__ __forceinline__ void ldsm_x4(uint32_t* r, uint32_t addr) {
    asm volatile("ldmatrix.sync.aligned.m8n8.x4.shared.b16 {%0,%1,%2,%3}, [%4];"
                 : "=r"(r[0]), "=r"(r[1]), "=r"(r[2]), "=r"(r[3])
                 : "r"(addr));
}

__device__ __forceinline__ void mma_bf16(float* d, const uint32_t* a, const uint32_t* b) {
    asm volatile(
        "mma.sync.aligned.m16n8k16.row.col.f32.bf16.bf16.f32 "
        "{%0,%1,%2,%3}, {%4,%5,%6,%7}, {%8,%9}, {%0,%1,%2,%3};"
        : "+f"(d[0]), "+f"(d[1]), "+f"(d[2]), "+f"(d[3])
        : "r"(a[0]), "r"(a[1]), "r"(a[2]), "r"(a[3]), "r"(b[0]), "r"(b[1]));
}

// single dynamic-smem symbol shared by all kernels
extern __shared__ char dynsm[];

// ---------------- CSR build --------------------------------------------------
__global__ void deg_kernel(const int* __restrict__ dst, int E) {
    int e = blockIdx.x * blockDim.x + threadIdx.x;
    if (e < E) atomicAdd(&g_deg[__ldg(dst + e)], 1);
}
__global__ void scan1_kernel() {
    __shared__ int sm[1024];
    int i = blockIdx.x * 1024 + threadIdx.x;
    int v = (i < NN) ? g_deg[i] : 0;
    sm[threadIdx.x] = v;
    __syncthreads();
    for (int off = 1; off < 1024; off <<= 1) {
        int t = (threadIdx.x >= off) ? sm[threadIdx.x - off] : 0;
        __syncthreads();
        sm[threadIdx.x] += t;
        __syncthreads();
    }
    if (i < NN) g_scan[i] = sm[threadIdx.x];
    if (threadIdx.x == 1023) g_bsum[blockIdx.x] = sm[1023];
}
__global__ void scan2_kernel() {
    int run = 0;
    for (int b = 0; b < NBLK_SCAN; b++) { g_boff[b] = run; run += g_bsum[b]; }
}
__global__ void scan3_kernel() {
    int i = blockIdx.x * blockDim.x + threadIdx.x;
    if (i >= NN) return;
    int r = g_boff[i >> 10] + g_scan[i] - g_deg[i];
    g_rowptr[i] = r;
    g_cursor[i] = r;
}
__global__ void fill_kernel(const int* __restrict__ src,
                            const int* __restrict__ dst, int E) {
    int e = blockIdx.x * blockDim.x + threadIdx.x;
    if (e >= E) return;
    int d = __ldg(dst + e);
    int pos = atomicAdd(&g_cursor[d], 1);
    g_srcs[pos] = __ldg(src + e);
}

// ---------------- gather-mean (warp/node, 4-way unroll) → bf16 hi/lo --------
__global__ void gather_kernel(const float4* __restrict__ x4) {
    int node = (blockIdx.x * blockDim.x + threadIdx.x) >> 5;
    int lane = threadIdx.x & 31;
    if (node >= NN) return;
    int i   = g_rowptr[node];
    int deg = g_deg[node];
    int end = i + deg;
    float4 a0 = make_float4(0.f, 0.f, 0.f, 0.f);
    float4 a1 = a0, a2 = a0, a3 = a0;
    for (; i + 4 <= end; i += 4) {
        int s0 = __ldg(&g_srcs[i]);
        int s1 = __ldg(&g_srcs[i + 1]);
        int s2 = __ldg(&g_srcs[i + 2]);
        int s3 = __ldg(&g_srcs[i + 3]);
        float4 v0 = __ldg(x4 + (size_t)s0 * 32 + lane);
        float4 v1 = __ldg(x4 + (size_t)s1 * 32 + lane);
        float4 v2 = __ldg(x4 + (size_t)s2 * 32 + lane);
        float4 v3 = __ldg(x4 + (size_t)s3 * 32 + lane);
        a0.x += v0.x; a0.y += v0.y; a0.z += v0.z; a0.w += v0.w;
        a1.x += v1.x; a1.y += v1.y; a1.z += v1.z; a1.w += v1.w;
        a2.x += v2.x; a2.y += v2.y; a2.z += v2.z; a2.w += v2.w;
        a3.x += v3.x; a3.y += v3.y; a3.z += v3.z; a3.w += v3.w;
    }
    for (; i < end; i++) {
        int s = __ldg(&g_srcs[i]);
        float4 v = __ldg(x4 + (size_t)s * 32 + lane);
        a0.x += v.x; a0.y += v.y; a0.z += v.z; a0.w += v.w;
    }
    float iv = 1.f / fmaxf((float)deg, 1.f);
    float m[4];
    m[0] = (a0.x + a1.x + a2.x + a3.x) * iv;
    m[1] = (a0.y + a1.y + a2.y + a3.y) * iv;
    m[2] = (a0.z + a1.z + a2.z + a3.z) * iv;
    m[3] = (a0.w + a1.w + a2.w + a3.w) * iv;
    __nv_bfloat16 h[4], l[4];
#pragma unroll
    for (int j = 0; j < 4; j++) split_bf16(m[j], h[j], l[j]);
    size_t o2 = ((size_t)node * 32 + lane) * 2;
    ((__nv_bfloat162*)g_mhi)[o2]     = __nv_bfloat162(h[0], h[1]);
    ((__nv_bfloat162*)g_mhi)[o2 + 1] = __nv_bfloat162(h[2], h[3]);
    ((__nv_bfloat162*)g_mlo)[o2]     = __nv_bfloat162(l[0], l[1]);
    ((__nv_bfloat162*)g_mlo)[o2 + 1] = __nv_bfloat162(l[2], l[3]);
}

// ---------------- input x → hi/lo bf16 --------------------------------------
__global__ void xconv_kernel(const float4* __restrict__ x4) {
    int i = blockIdx.x * blockDim.x + threadIdx.x;
    if (i >= NN * 32) return;
    float4 v = __ldg(x4 + i);
    __nv_bfloat16 h[4], l[4];
    split_bf16(v.x, h[0], l[0]); split_bf16(v.y, h[1], l[1]);
    split_bf16(v.z, h[2], l[2]); split_bf16(v.w, h[3], l[3]);
    size_t o2 = (size_t)i * 2;
    ((__nv_bfloat162*)g_xhi)[o2]     = __nv_bfloat162(h[0], h[1]);
    ((__nv_bfloat162*)g_xhi)[o2 + 1] = __nv_bfloat162(h[2], h[3]);
    ((__nv_bfloat162*)g_xlo)[o2]     = __nv_bfloat162(l[0], l[1]);
    ((__nv_bfloat162*)g_xlo)[o2 + 1] = __nv_bfloat162(l[2], l[3]);
}

// ---------------- weights → concat K-major hi/lo ----------------------------
// Wcat[col][k] : k<128 from Wl[col][k], k>=128 from Wr[col][k-128]
__global__ void wconv_kernel(const float* __restrict__ Wl,
                             const float* __restrict__ Wr) {
    int idx = blockIdx.x * blockDim.x + threadIdx.x;
    if (idx >= 2 * DD * DD) return;
    int half = idx >> 14;
    int id   = idx & 16383;
    int col  = id >> 7, k = id & 127;
    float v = half ? __ldg(Wr + id) : __ldg(Wl + id);
    int pos = col * 256 + half * 128 + k;
    __nv_bfloat16 h, l;
    split_bf16(v, h, l);
    g_whi[pos] = h;
    g_wlo[pos] = l;
}

// ---------------- HMMA split-bf16 GEMM: h = Acat @ Wcat^T -------------------
// CTA 128x128 tile; 8 warps in 4x2 (warp tile 32x64); K=256 in 4 chunks of 64;
// 3 precision passes (hi*hi + hi*lo + lo*hi). Smem row stride 144B (bank-free).
#define TS 18432          // bytes per smem tile (128 rows * 144)
__global__ __launch_bounds__(256, 2) void gemm_mma_kernel() {
    char* sm = dynsm;
    uint32_t sb = smem_to_u32(sm);

    int tid = threadIdx.x, lane = tid & 31, wid = tid >> 5;
    int row0 = blockIdx.x * 128;
    int wr = wid >> 1, wc = wid & 1;

    float acc[2][8][4];
#pragma unroll
    for (int bm = 0; bm < 2; bm++)
#pragma unroll
        for (int j = 0; j < 8; j++)
#pragma unroll
            for (int q = 0; q < 4; q++) acc[bm][j][q] = 0.f;

    const uint4* whi4 = (const uint4*)g_whi;
    const uint4* wlo4 = (const uint4*)g_wlo;

    // per-thread ldmatrix address components
    int a_min  = (lane & 7) + ((lane >> 3) & 1) * 8;   // row within m16
    int a_koff = (lane >> 4) * 16;                     // k byte offset (0|16)
    int b_nin  = (lane & 7) + ((lane >> 4) & 1) * 8;   // row within n16 pair
    int b_koff = ((lane >> 3) & 1) * 16;

    for (int kc = 0; kc < 4; kc++) {
        if (kc) __syncthreads();
        const uint4* srcHi = (kc < 2) ? (const uint4*)g_xhi : (const uint4*)g_mhi;
        const uint4* srcLo = (kc < 2) ? (const uint4*)g_xlo : (const uint4*)g_mlo;
        int koff4 = (kc & 1) * 8;
#pragma unroll
        for (int l = 0; l < 4; l++) {
            int i = tid + l * 256;
            int r = i >> 3, c = i & 7;
            int grow = row0 + r;
            uint4 vh = make_uint4(0, 0, 0, 0), vl = vh;
            if (grow < NN) {
                vh = __ldg(srcHi + (size_t)grow * 16 + koff4 + c);
                vl = __ldg(srcLo + (size_t)grow * 16 + koff4 + c);
            }
            *(uint4*)(sm + r * 144 + c * 16)      = vh;
            *(uint4*)(sm + TS + r * 144 + c * 16) = vl;
        }
#pragma unroll
        for (int l = 0; l < 4; l++) {
            int i = tid + l * 256;
            int n = i >> 3, c = i & 7;
            uint4 vh = __ldg(whi4 + n * 32 + kc * 8 + c);
            uint4 vl = __ldg(wlo4 + n * 32 + kc * 8 + c);
            *(uint4*)(sm + 2 * TS + n * 144 + c * 16) = vh;
            *(uint4*)(sm + 3 * TS + n * 144 + c * 16) = vl;
        }
        __syncthreads();

        uint32_t aBase[2] = {sb, sb + TS};              // Ah, Al
        uint32_t bBase[2] = {sb + 2 * TS, sb + 3 * TS}; // Bh, Bl
        const int pa[3] = {0, 0, 1};   // pass -> A hi/lo
        const int pb[3] = {0, 1, 0};   // pass -> B hi/lo
#pragma unroll
        for (int p = 0; p < 3; p++) {
            uint32_t Ab = aBase[pa[p]];
            uint32_t Bb = bBase[pb[p]];
#pragma unroll
            for (int ks = 0; ks < 4; ks++) {
                uint32_t a[2][4];
#pragma unroll
                for (int bm = 0; bm < 2; bm++)
                    ldsm_x4(a[bm], Ab + (uint32_t)((wr * 32 + bm * 16 + a_min) * 144
                                                   + ks * 32 + a_koff));
                uint32_t b[8][2];
#pragma unroll
                for (int jp = 0; jp < 4; jp++) {
                    uint32_t t[4];
                    ldsm_x4(t, Bb + (uint32_t)((wc * 64 + jp * 16 + b_nin) * 144
                                               + ks * 32 + b_koff));
                    b[jp * 2][0]     = t[0];
                    b[jp * 2][1]     = t[1];
                    b[jp * 2 + 1][0] = t[2];
                    b[jp * 2 + 1][1] = t[3];
                }
#pragma unroll
                for (int bm = 0; bm < 2; bm++)
#pragma unroll
                    for (int j = 0; j < 8; j++)
                        mma_bf16(acc[bm][j], a[bm], b[j]);
            }
        }
    }

    // epilogue: write h
    int mrow = wr * 32, ncol = wc * 64;
#pragma unroll
    for (int bm = 0; bm < 2; bm++) {
        int r_lo = row0 + mrow + bm * 16 + (lane >> 2);
        int r_hi = r_lo + 8;
#pragma unroll
        for (int j = 0; j < 8; j++) {
            int cb = ncol + j * 8 + (lane & 3) * 2;
            if (r_lo < NN)
                *(float2*)(g_h + (size_t)r_lo * DD + cb) =
                    make_float2(acc[bm][j][0], acc[bm][j][1]);
            if (r_hi < NN)
                *(float2*)(g_h + (size_t)r_hi * DD + cb) =
                    make_float2(acc[bm][j][2], acc[bm][j][3]);
        }
    }
}

// ---------------- BN column stats -------------------------------------------
__global__ void bnstat_kernel() {
    __shared__ float sa[256], sb[256];
    int tid = threadIdx.x;
    int c = tid & 127, half = tid >> 7;
    int r0 = blockIdx.x * 512;
    int r1 = min(r0 + 512, NN);
    float s = 0.f, s2 = 0.f;
    for (int row = r0 + half; row < r1; row += 2) {
        float v = g_h[(size_t)row * DD + c];
        s += v; s2 += v * v;
    }
    sa[tid] = s; sb[tid] = s2;
    __syncthreads();
    if (tid < 128) {
        atomicAdd(&g_sum[c],  sa[tid] + sa[tid + 128]);
        atomicAdd(&g_sum2[c], sb[tid] + sb[tid + 128]);
    }
}

__global__ void bnprep_kernel(const float* __restrict__ gamma,
                              const float* __restrict__ beta) {
    int c = threadIdx.x;
    float invN = 1.0f / (float)NN;
    float mu  = g_sum[c] * invN;
    float var = g_sum2[c] * invN - mu * mu;
    float rs  = rsqrtf(var + 1e-5f);
    float a   = gamma[c] * rs;
    g_scale[c] = a;
    g_shift[c] = beta[c] - mu * a;
}

// ---------------- BN apply + ReLU + residual + hi/lo split ------------------
__global__ void bnfin_kernel(const float4* __restrict__ xin4,
                             float4* __restrict__ xout4) {
    int i = blockIdx.x * blockDim.x + threadIdx.x;
    if (i >= NN * 32) return;
    int c4 = i & 31;
    float4 hv = ((const float4*)g_h)[i];
    float4 sc = ((const float4*)g_scale)[c4];
    float4 sh = ((const float4*)g_shift)[c4];
    float4 xv = __ldg(xin4 + i);
    float4 o;
    o.x = xv.x + fmaxf(0.f, hv.x * sc.x + sh.x);
    o.y = xv.y + fmaxf(0.f, hv.y * sc.y + sh.y);
    o.z = xv.z + fmaxf(0.f, hv.z * sc.z + sh.z);
    o.w = xv.w + fmaxf(0.f, hv.w * sc.w + sh.w);
    xout4[i] = o;
    __nv_bfloat16 h[4], l[4];
    split_bf16(o.x, h[0], l[0]); split_bf16(o.y, h[1], l[1]);
    split_bf16(o.z, h[2], l[2]); split_bf16(o.w, h[3], l[3]);
    size_t o2 = (size_t)i * 2;
    ((__nv_bfloat162*)g_xhi)[o2]     = __nv_bfloat162(h[0], h[1]);
    ((__nv_bfloat162*)g_xhi)[o2 + 1] = __nv_bfloat162(h[2], h[3]);
    ((__nv_bfloat162*)g_xlo)[o2]     = __nv_bfloat162(l[0], l[1]);
    ((__nv_bfloat162*)g_xlo)[o2 + 1] = __nv_bfloat162(l[2], l[3]);
}

// ---------------- final linear ----------------------------------------------
__global__ __launch_bounds__(256) void final_kernel(
    const float4* __restrict__ x4,
    const float4* __restrict__ W4,
    const float* __restrict__ bias,
    float* __restrict__ out) {
    float4* Xs = (float4*)dynsm;
    float4* Wk = Xs + 128 * 32;
    int tid  = threadIdx.x;
    int row0 = blockIdx.x * 128;

    for (int idx = tid; idx < 128 * 32; idx += 256) {
        int r = idx >> 5, k4 = idx & 31;
        int row = row0 + r;
        Xs[idx] = (row < NN) ? __ldg(x4 + (size_t)row * 32 + k4)
                             : make_float4(0.f, 0.f, 0.f, 0.f);
    }
    for (int idx = tid; idx < CC * 32; idx += 256) Wk[idx] = __ldg(W4 + idx);
    __syncthreads();

    for (int o = tid; o < 128 * CC; o += 256) {
        int r = o / CC, c = o - r * CC;
        int row = row0 + r;
        if (row >= NN) continue;
        float acc = 0.f;
#pragma unroll
        for (int k4 = 0; k4 < 32; k4++) {
            float4 a = Xs[r * 32 + k4];
            float4 w = Wk[c * 32 + k4];
            acc += a.x * w.x + a.y * w.y + a.z * w.z + a.w * w.w;
        }
        out[(size_t)row * CC + c] = acc + __ldg(bias + c);
    }
}

// ---------------- host orchestration ----------------------------------------
extern "C" void kernel_launch(void* const* d_in, const int* in_sizes, int n_in,
                              void* d_out, int out_size) {
    const float* x  = (const float*)d_in[0];
    const int*   ei = (const int*)d_in[1];
    int E = in_sizes[1] / 2;
    const int* src = ei;
    const int* dst = ei + E;

    void *deg_p, *sum_p, *sum2_p, *xA_p, *xB_p;
    cudaGetSymbolAddress(&deg_p,  g_deg);
    cudaGetSymbolAddress(&sum_p,  g_sum);
    cudaGetSymbolAddress(&sum2_p, g_sum2);
    cudaGetSymbolAddress(&xA_p,   g_xA);
    cudaGetSymbolAddress(&xB_p,   g_xB);

    const int SMEM_MMA   = 4 * TS;   // 73728
    const int SMEM_FINAL = (128 * 32 + CC * 32) * (int)sizeof(float4);
    cudaFuncSetAttribute(gemm_mma_kernel, cudaFuncAttributeMaxDynamicSharedMemorySize, SMEM_MMA);
    cudaFuncSetAttribute(final_kernel,    cudaFuncAttributeMaxDynamicSharedMemorySize, SMEM_FINAL);

    // ---- CSR build ----
    cudaMemsetAsync(deg_p, 0, NN * sizeof(int), 0);
    deg_kernel<<<(E + 255) / 256, 256>>>(dst, E);
    scan1_kernel<<<NBLK_SCAN, 1024>>>();
    scan2_kernel<<<1, 1>>>();
    scan3_kernel<<<(NN + 255) / 256, 256>>>();
    fill_kernel<<<(E + 255) / 256, 256>>>(src, dst, E);

    xconv_kernel<<<(NN * 32 + 255) / 256, 256>>>((const float4*)x);

    const float* xin = x;
    float* xbufs[2] = {(float*)xA_p, (float*)xB_p};

    for (int L = 0; L < 3; L++) {
        const float* Wl = (const float*)d_in[2 + 5 * L];
        const float* Wr = (const float*)d_in[4 + 5 * L];
        const float* bg = (const float*)d_in[5 + 5 * L];
        const float* bb = (const float*)d_in[6 + 5 * L];
        float* xout = xbufs[L & 1];

        cudaMemsetAsync(sum_p, 0, DD * sizeof(float), 0);
        cudaMemsetAsync(sum2_p, 0, DD * sizeof(float), 0);

        gather_kernel<<<(NN * 32 + 255) / 256, 256>>>((const float4*)xin);
        wconv_kernel<<<(2 * DD * DD + 255) / 256, 256>>>(Wl, Wr);
        gemm_mma_kernel<<<(NN + 127) / 128, 256, SMEM_MMA>>>();
        bnstat_kernel<<<(NN + 511) / 512, 256>>>();
        bnprep_kernel<<<1, DD>>>(bg, bb);
        bnfin_kernel<<<(NN * 32 + 255) / 256, 256>>>(
            (const float4*)xin, (float4*)xout);
        xin = xout;
    }

    final_kernel<<<(NN + 127) / 128, 256, SMEM_FINAL>>>(
        (const float4*)xin, (const float4*)d_in[17],
        (const float*)d_in[18], (float*)d_out);
}

// round 7
// speedup vs baseline: 1.8179x; 1.1140x over previous
#include <cuda_runtime.h>
#include <cuda_bf16.h>
#include <cstdint>

#define NN 100000
#define DD 128
#define CC 47
#define EMAX 1700000
#define NBLK_SCAN 98

// ---------------- scratch ----------------------------------------------------
__device__ __align__(128) float g_h[(size_t)NN * DD];
__device__ __align__(128) __nv_bfloat16 g_xhi[(size_t)NN * DD];
__device__ __align__(128) __nv_bfloat16 g_xlo[(size_t)NN * DD];
__device__ __align__(128) __nv_bfloat16 g_mhi[(size_t)NN * DD];
__device__ __align__(128) __nv_bfloat16 g_mlo[(size_t)NN * DD];
__device__ __align__(128) __nv_bfloat16 g_whi[3 * 2 * DD * DD];
__device__ __align__(128) __nv_bfloat16 g_wlo[3 * 2 * DD * DD];
__device__ __align__(128) float g_sum[DD];
__device__ __align__(128) float g_sum2[DD];
__device__ __align__(128) float g_scale[DD];
__device__ __align__(128) float g_shift[DD];
__device__ __align__(128) int   g_deg[NN];
__device__ __align__(128) int   g_scan[NN];
__device__ __align__(128) int   g_rowptr[NN];
__device__ __align__(128) int   g_cursor[NN];
__device__ __align__(128) int   g_srcs[EMAX];
__device__ __align__(128) int   g_bsum[128];
__device__ __align__(128) int   g_boff[128];

__device__ __forceinline__ void split_bf16(float v, __nv_bfloat16& hi, __nv_bfloat16& lo) {
    hi = __float2bfloat16(v);
    lo = __float2bfloat16(v - __bfloat162float(hi));
}

__device__ __forceinline__ uint32_t smem_to_u32(const void* p) {
    uint32_t a;
    asm("{ .reg .u64 t; cvta.to.shared.u64 t, %1; cvt.u32.u64 %0, t; }"
        : "=r"(a) : "l"(p));
    return a;
}

__device__ __forceinline__ void ldsm_x4(uint32_t* r, uint32_t addr) {
    asm volatile("ldmatrix.sync.aligned.m8n8.x4.shared.b16 {%0,%1,%2,%3}, [%4];"
                 : "=r"(r[0]), "=r"(r[1]), "=r"(r[2]), "=r"(r[3])
                 : "r"(addr));
}

__device__ __forceinline__ void mma_bf16(float* d, const uint32_t* a, const uint32_t* b) {
    asm volatile(
        "mma.sync.aligned.m16n8k16.row.col.f32.bf16.bf16.f32 "
        "{%0,%1,%2,%3}, {%4,%5,%6,%7}, {%8,%9}, {%0,%1,%2,%3};"
        : "+f"(d[0]), "+f"(d[1]), "+f"(d[2]), "+f"(d[3])
        : "r"(a[0]), "r"(a[1]), "r"(a[2]), "r"(a[3]), "r"(b[0]), "r"(b[1]));
}

__device__ __forceinline__ void cpa16(uint32_t dst, const void* src, int nbytes) {
    asm volatile("cp.async.cg.shared.global [%0], [%1], 16, %2;"
                 :: "r"(dst), "l"(src), "r"(nbytes));
}

extern __shared__ char dynsm[];

// ---------------- CSR build --------------------------------------------------
__global__ void deg_kernel(const int* __restrict__ dst, int E) {
    int e = blockIdx.x * blockDim.x + threadIdx.x;
    if (e < E) atomicAdd(&g_deg[__ldg(dst + e)], 1);
}
__global__ void scan1_kernel() {
    __shared__ int sm[1024];
    int i = blockIdx.x * 1024 + threadIdx.x;
    int v = (i < NN) ? g_deg[i] : 0;
    sm[threadIdx.x] = v;
    __syncthreads();
    for (int off = 1; off < 1024; off <<= 1) {
        int t = (threadIdx.x >= off) ? sm[threadIdx.x - off] : 0;
        __syncthreads();
        sm[threadIdx.x] += t;
        __syncthreads();
    }
    if (i < NN) g_scan[i] = sm[threadIdx.x];
    if (threadIdx.x == 1023) g_bsum[blockIdx.x] = sm[1023];
}
__global__ void scan2_kernel() {
    int run = 0;
    for (int b = 0; b < NBLK_SCAN; b++) { g_boff[b] = run; run += g_bsum[b]; }
}
__global__ void scan3_kernel() {
    int i = blockIdx.x * blockDim.x + threadIdx.x;
    if (i >= NN) return;
    int r = g_boff[i >> 10] + g_scan[i] - g_deg[i];
    g_rowptr[i] = r;
    g_cursor[i] = r;
}
__global__ void fill_kernel(const int* __restrict__ src,
                            const int* __restrict__ dst, int E) {
    int e = blockIdx.x * blockDim.x + threadIdx.x;
    if (e >= E) return;
    int d = __ldg(dst + e);
    int pos = atomicAdd(&g_cursor[d], 1);
    g_srcs[pos] = __ldg(src + e);
}

// ---------------- gather-mean from (hi,lo) bf16 ------------------------------
// warp per node; lanes 0-15 stream hi uint4s, lanes 16-31 the matching lo
// uint4s; shfl_xor(16) recombines. Output: mhi/mlo split of the mean.
__global__ void gather_kernel() {
    int node = (blockIdx.x * blockDim.x + threadIdx.x) >> 5;
    int lane = threadIdx.x & 31;
    if (node >= NN) return;
    int seg = lane & 15;
    const uint4* base = (lane < 16) ? (const uint4*)g_xhi : (const uint4*)g_xlo;
    int i = g_rowptr[node], deg = g_deg[node], end = i + deg;
    float acc[8];
#pragma unroll
    for (int f = 0; f < 8; f++) acc[f] = 0.f;

    for (; i + 4 <= end; i += 4) {
        int s0 = __ldg(&g_srcs[i]);
        int s1 = __ldg(&g_srcs[i + 1]);
        int s2 = __ldg(&g_srcs[i + 2]);
        int s3 = __ldg(&g_srcs[i + 3]);
        uint4 v0 = __ldg(base + (size_t)s0 * 16 + seg);
        uint4 v1 = __ldg(base + (size_t)s1 * 16 + seg);
        uint4 v2 = __ldg(base + (size_t)s2 * 16 + seg);
        uint4 v3 = __ldg(base + (size_t)s3 * 16 + seg);
        const uint4* vs[4] = {&v0, &v1, &v2, &v3};
#pragma unroll
        for (int e2 = 0; e2 < 4; e2++) {
            const __nv_bfloat162* p = (const __nv_bfloat162*)vs[e2];
#pragma unroll
            for (int q = 0; q < 4; q++) {
                float2 f = __bfloat1622float2(p[q]);
                acc[2 * q] += f.x; acc[2 * q + 1] += f.y;
            }
        }
    }
    for (; i < end; i++) {
        int s = __ldg(&g_srcs[i]);
        uint4 v = __ldg(base + (size_t)s * 16 + seg);
        const __nv_bfloat162* p = (const __nv_bfloat162*)&v;
#pragma unroll
        for (int q = 0; q < 4; q++) {
            float2 f = __bfloat1622float2(p[q]);
            acc[2 * q] += f.x; acc[2 * q + 1] += f.y;
        }
    }

    float iv = 1.f / fmaxf((float)deg, 1.f);
    uint32_t outw[4];
#pragma unroll
    for (int q = 0; q < 4; q++) {
        float m0 = (acc[2 * q]     + __shfl_xor_sync(0xffffffffu, acc[2 * q],     16)) * iv;
        float m1 = (acc[2 * q + 1] + __shfl_xor_sync(0xffffffffu, acc[2 * q + 1], 16)) * iv;
        __nv_bfloat16 h0, l0, h1, l1;
        split_bf16(m0, h0, l0);
        split_bf16(m1, h1, l1);
        __nv_bfloat162 pk = (lane < 16) ? __nv_bfloat162(h0, h1) : __nv_bfloat162(l0, l1);
        outw[q] = *(uint32_t*)&pk;
    }
    uint4* dstA = (lane < 16) ? (uint4*)g_mhi : (uint4*)g_mlo;
    dstA[(size_t)node * 16 + seg] = make_uint4(outw[0], outw[1], outw[2], outw[3]);
}

// ---------------- input x → hi/lo bf16 --------------------------------------
__global__ void xconv_kernel(const float4* __restrict__ x4) {
    int i = blockIdx.x * blockDim.x + threadIdx.x;
    if (i >= NN * 32) return;
    float4 v = __ldg(x4 + i);
    __nv_bfloat16 h[4], l[4];
    split_bf16(v.x, h[0], l[0]); split_bf16(v.y, h[1], l[1]);
    split_bf16(v.z, h[2], l[2]); split_bf16(v.w, h[3], l[3]);
    size_t o2 = (size_t)i * 2;
    ((__nv_bfloat162*)g_xhi)[o2]     = __nv_bfloat162(h[0], h[1]);
    ((__nv_bfloat162*)g_xhi)[o2 + 1] = __nv_bfloat162(h[2], h[3]);
    ((__nv_bfloat162*)g_xlo)[o2]     = __nv_bfloat162(l[0], l[1]);
    ((__nv_bfloat162*)g_xlo)[o2 + 1] = __nv_bfloat162(l[2], l[3]);
}

// ---------------- all-layer weights → concat K-major hi/lo ------------------
__global__ void wconv_kernel(const float* __restrict__ Wl1, const float* __restrict__ Wr1,
                             const float* __restrict__ Wl2, const float* __restrict__ Wr2,
                             const float* __restrict__ Wl3, const float* __restrict__ Wr3) {
    int idx = blockIdx.x * blockDim.x + threadIdx.x;
    if (idx >= 3 * 2 * DD * DD) return;
    int l    = idx >> 15;          // layer
    int rem  = idx & 32767;
    int half = rem >> 14;          // 0=Wl, 1=Wr
    int id   = rem & 16383;
    int col  = id >> 7, k = id & 127;
    const float* tab[6] = {Wl1, Wr1, Wl2, Wr2, Wl3, Wr3};
    float v = __ldg(tab[l * 2 + half] + id);
    int pos = l * 32768 + col * 256 + half * 128 + k;
    __nv_bfloat16 h, lo;
    split_bf16(v, h, lo);
    g_whi[pos] = h;
    g_wlo[pos] = lo;
}

// ---------------- pipelined HMMA split-bf16 GEMM ----------------------------
// h = [x | mean] @ [Wl;Wr]^T.  CTA 128x128; 8 warps (4x2, warp 32x64);
// K=256 in 8 chunks of 32, 2-stage cp.async pipeline; smem row stride 80B
// (ldmatrix banks 0,20,8,28,16,4,24,12: conflict-free).
// BN column sums accumulated in the epilogue.
#define ROWB 80
#define TILE_B (128 * ROWB)        // 10240
#define ST_A_HI 0
#define ST_A_LO TILE_B
#define ST_B_HI (2 * TILE_B)
#define ST_B_LO (3 * TILE_B)
#define STAGE_B (4 * TILE_B)       // 40960

__device__ __forceinline__ void load_chunk(uint32_t sb, char* dummy, int stage, int kc,
                                           int row0, int tid,
                                           const uint4* whi4, const uint4* wlo4) {
    uint32_t sbase = sb + stage * STAGE_B;
    const uint4* aH = (kc < 4) ? (const uint4*)g_xhi : (const uint4*)g_mhi;
    const uint4* aL = (kc < 4) ? (const uint4*)g_xlo : (const uint4*)g_mlo;
    int ku = (kc & 3) * 4;
#pragma unroll
    for (int l = 0; l < 2; l++) {
        int idx = tid + l * 256;           // 0..511
        int r = idx >> 2, c = idx & 3;
        int grow = row0 + r;
        int nb = (grow < NN) ? 16 : 0;
        size_t srow = (size_t)min(grow, NN - 1) * 16;
        uint32_t d = sbase + r * ROWB + c * 16;
        cpa16(d + ST_A_HI, aH + srow + ku + c, nb);
        cpa16(d + ST_A_LO, aL + srow + ku + c, nb);
        cpa16(d + ST_B_HI, whi4 + r * 32 + kc * 4 + c, 16);
        cpa16(d + ST_B_LO, wlo4 + r * 32 + kc * 4 + c, 16);
    }
    asm volatile("cp.async.commit_group;" ::: "memory");
}

__global__ __launch_bounds__(256, 2) void gemm_mma_kernel(int layer) {
    char* sm = dynsm;
    uint32_t sb = smem_to_u32(sm);
    __shared__ float ssum[DD], ssum2[DD];

    int tid = threadIdx.x, lane = tid & 31, wid = tid >> 5;
    int row0 = blockIdx.x * 128;
    int wr = wid >> 1, wc = wid & 1;
    if (tid < DD) { ssum[tid] = 0.f; ssum2[tid] = 0.f; }

    const uint4* whi4 = (const uint4*)g_whi + layer * 4096;
    const uint4* wlo4 = (const uint4*)g_wlo + layer * 4096;

    float acc[2][8][4];
#pragma unroll
    for (int bm = 0; bm < 2; bm++)
#pragma unroll
        for (int j = 0; j < 8; j++)
#pragma unroll
            for (int q = 0; q < 4; q++) acc[bm][j][q] = 0.f;

    int a_min  = lane & 15;
    int a_koff = (lane >> 4) * 16;
    int b_nin  = (lane & 7) + ((lane >> 4) & 1) * 8;
    int b_koff = ((lane >> 3) & 1) * 16;

    load_chunk(sb, sm, 0, 0, row0, tid, whi4, wlo4);

    const int pa[3] = {0, 0, 1};
    const int pb[3] = {0, 1, 0};

    for (int kc = 0; kc < 8; kc++) {
        int st = kc & 1;
        if (kc < 7) {
            load_chunk(sb, sm, st ^ 1, kc + 1, row0, tid, whi4, wlo4);
            asm volatile("cp.async.wait_group 1;" ::: "memory");
        } else {
            asm volatile("cp.async.wait_group 0;" ::: "memory");
        }
        __syncthreads();

        uint32_t sbase = sb + st * STAGE_B;
#pragma unroll
        for (int p = 0; p < 3; p++) {
            uint32_t Ab = sbase + (pa[p] ? ST_A_LO : ST_A_HI);
            uint32_t Bb = sbase + (pb[p] ? ST_B_LO : ST_B_HI);
#pragma unroll
            for (int ks = 0; ks < 2; ks++) {
                uint32_t a[2][4];
#pragma unroll
                for (int bm = 0; bm < 2; bm++)
                    ldsm_x4(a[bm], Ab + (uint32_t)((wr * 32 + bm * 16 + a_min) * ROWB
                                                   + ks * 32 + a_koff));
                uint32_t b[8][2];
#pragma unroll
                for (int jp = 0; jp < 4; jp++) {
                    uint32_t t[4];
                    ldsm_x4(t, Bb + (uint32_t)((wc * 64 + jp * 16 + b_nin) * ROWB
                                               + ks * 32 + b_koff));
                    b[jp * 2][0]     = t[0];
                    b[jp * 2][1]     = t[1];
                    b[jp * 2 + 1][0] = t[2];
                    b[jp * 2 + 1][1] = t[3];
                }
#pragma unroll
                for (int bm = 0; bm < 2; bm++)
#pragma unroll
                    for (int j = 0; j < 8; j++)
                        mma_bf16(acc[bm][j], a[bm], b[j]);
            }
        }
        __syncthreads();
    }

    // epilogue: write h + BN column sums
    int mrow = wr * 32, ncol = wc * 64;
    float cs[16], cs2[16];
#pragma unroll
    for (int t = 0; t < 16; t++) { cs[t] = 0.f; cs2[t] = 0.f; }

#pragma unroll
    for (int bm = 0; bm < 2; bm++) {
        int r_lo = row0 + mrow + bm * 16 + (lane >> 2);
        int r_hi = r_lo + 8;
#pragma unroll
        for (int j = 0; j < 8; j++) {
            int cb = ncol + j * 8 + (lane & 3) * 2;
            float v0 = acc[bm][j][0], v1 = acc[bm][j][1];
            float v2 = acc[bm][j][2], v3 = acc[bm][j][3];
            cs[j * 2]      += v0 + v2;
            cs2[j * 2]     += v0 * v0 + v2 * v2;
            cs[j * 2 + 1]  += v1 + v3;
            cs2[j * 2 + 1] += v1 * v1 + v3 * v3;
            if (r_lo < NN)
                *(float2*)(g_h + (size_t)r_lo * DD + cb) = make_float2(v0, v1);
            if (r_hi < NN)
                *(float2*)(g_h + (size_t)r_hi * DD + cb) = make_float2(v2, v3);
        }
    }
    // reduce across the 8 lanes sharing the same columns (lane>>2 varies)
#pragma unroll
    for (int t = 0; t < 16; t++) {
        cs[t]  += __shfl_xor_sync(0xffffffffu, cs[t], 4);
        cs[t]  += __shfl_xor_sync(0xffffffffu, cs[t], 8);
        cs[t]  += __shfl_xor_sync(0xffffffffu, cs[t], 16);
        cs2[t] += __shfl_xor_sync(0xffffffffu, cs2[t], 4);
        cs2[t] += __shfl_xor_sync(0xffffffffu, cs2[t], 8);
        cs2[t] += __shfl_xor_sync(0xffffffffu, cs2[t], 16);
    }
    if (lane < 4) {
#pragma unroll
        for (int j = 0; j < 8; j++) {
#pragma unroll
            for (int t = 0; t < 2; t++) {
                int col = ncol + j * 8 + lane * 2 + t;
                atomicAdd(&ssum[col],  cs[j * 2 + t]);
                atomicAdd(&ssum2[col], cs2[j * 2 + t]);
            }
        }
    }
    __syncthreads();
    if (tid < DD) {
        atomicAdd(&g_sum[tid],  ssum[tid]);
        atomicAdd(&g_sum2[tid], ssum2[tid]);
    }
}

// ---------------- BN scale/shift (+ reset sums for next layer) --------------
__global__ void bnprep_kernel(const float* __restrict__ gamma,
                              const float* __restrict__ beta) {
    int c = threadIdx.x;
    float invN = 1.0f / (float)NN;
    float mu  = g_sum[c] * invN;
    float var = g_sum2[c] * invN - mu * mu;
    float rs  = rsqrtf(var + 1e-5f);
    float a   = gamma[c] * rs;
    g_scale[c] = a;
    g_shift[c] = beta[c] - mu * a;
    g_sum[c] = 0.f;
    g_sum2[c] = 0.f;
}

// ---------------- BN apply + ReLU + residual, in-place on (hi,lo) -----------
__global__ void bnfin_kernel() {
    int i = blockIdx.x * blockDim.x + threadIdx.x;   // one uint4 (8 features)
    if (i >= NN * 16) return;
    int seg = i & 15;
    uint4 vh = ((const uint4*)g_xhi)[i];
    uint4 vl = ((const uint4*)g_xlo)[i];
    const __nv_bfloat162* ph = (const __nv_bfloat162*)&vh;
    const __nv_bfloat162* pl = (const __nv_bfloat162*)&vl;
    int row = i >> 4;
    const float4* h4 = (const float4*)(g_h + (size_t)row * DD + seg * 8);
    float4 hv0 = h4[0], hv1 = h4[1];
    float4 sc0 = ((const float4*)g_scale)[seg * 2];
    float4 sc1 = ((const float4*)g_scale)[seg * 2 + 1];
    float4 sh0 = ((const float4*)g_shift)[seg * 2];
    float4 sh1 = ((const float4*)g_shift)[seg * 2 + 1];

    float xv[8], hh[8], scv[8], shv[8];
#pragma unroll
    for (int q = 0; q < 4; q++) {
        float2 fh = __bfloat1622float2(ph[q]);
        float2 fl = __bfloat1622float2(pl[q]);
        xv[2 * q] = fh.x + fl.x; xv[2 * q + 1] = fh.y + fl.y;
    }
    hh[0]=hv0.x; hh[1]=hv0.y; hh[2]=hv0.z; hh[3]=hv0.w;
    hh[4]=hv1.x; hh[5]=hv1.y; hh[6]=hv1.z; hh[7]=hv1.w;
    scv[0]=sc0.x; scv[1]=sc0.y; scv[2]=sc0.z; scv[3]=sc0.w;
    scv[4]=sc1.x; scv[5]=sc1.y; scv[6]=sc1.z; scv[7]=sc1.w;
    shv[0]=sh0.x; shv[1]=sh0.y; shv[2]=sh0.z; shv[3]=sh0.w;
    shv[4]=sh1.x; shv[5]=sh1.y; shv[6]=sh1.z; shv[7]=sh1.w;

    uint32_t oh[4], ol[4];
#pragma unroll
    for (int q = 0; q < 4; q++) {
        float o0 = xv[2 * q]     + fmaxf(0.f, hh[2 * q]     * scv[2 * q]     + shv[2 * q]);
        float o1 = xv[2 * q + 1] + fmaxf(0.f, hh[2 * q + 1] * scv[2 * q + 1] + shv[2 * q + 1]);
        __nv_bfloat16 h0, l0, h1, l1;
        split_bf16(o0, h0, l0);
        split_bf16(o1, h1, l1);
        __nv_bfloat162 pkh(h0, h1), pkl(l0, l1);
        oh[q] = *(uint32_t*)&pkh;
        ol[q] = *(uint32_t*)&pkl;
    }
    ((uint4*)g_xhi)[i] = make_uint4(oh[0], oh[1], oh[2], oh[3]);
    ((uint4*)g_xlo)[i] = make_uint4(ol[0], ol[1], ol[2], ol[3]);
}

// ---------------- final linear: out = x @ lin_W^T + lin_b -------------------
__global__ __launch_bounds__(256) void final_kernel(
    const float4* __restrict__ W4,
    const float* __restrict__ bias,
    float* __restrict__ out) {
    float4* Xs = (float4*)dynsm;            // 128 rows * 32 float4
    float4* Wk = Xs + 128 * 32;             // 47 rows * 32 float4
    int tid  = threadIdx.x;
    int row0 = blockIdx.x * 128;

    for (int idx = tid; idx < 128 * 16; idx += 256) {
        int r = idx >> 4, s = idx & 15;
        int row = row0 + r;
        float4 a = make_float4(0.f, 0.f, 0.f, 0.f), b = a;
        if (row < NN) {
            uint4 vh = ((const uint4*)g_xhi)[(size_t)row * 16 + s];
            uint4 vl = ((const uint4*)g_xlo)[(size_t)row * 16 + s];
            const __nv_bfloat162* ph = (const __nv_bfloat162*)&vh;
            const __nv_bfloat162* pl = (const __nv_bfloat162*)&vl;
            float2 f0 = __bfloat1622float2(ph[0]), g0 = __bfloat1622float2(pl[0]);
            float2 f1 = __bfloat1622float2(ph[1]), g1 = __bfloat1622float2(pl[1]);
            float2 f2 = __bfloat1622float2(ph[2]), g2 = __bfloat1622float2(pl[2]);
            float2 f3 = __bfloat1622float2(ph[3]), g3 = __bfloat1622float2(pl[3]);
            a = make_float4(f0.x + g0.x, f0.y + g0.y, f1.x + g1.x, f1.y + g1.y);
            b = make_float4(f2.x + g2.x, f2.y + g2.y, f3.x + g3.x, f3.y + g3.y);
        }
        Xs[r * 32 + s * 2]     = a;
        Xs[r * 32 + s * 2 + 1] = b;
    }
    for (int idx = tid; idx < CC * 32; idx += 256) Wk[idx] = __ldg(W4 + idx);
    __syncthreads();

    for (int o = tid; o < 128 * CC; o += 256) {
        int r = o / CC, c = o - r * CC;
        int row = row0 + r;
        if (row >= NN) continue;
        float acc = 0.f;
#pragma unroll
        for (int k4 = 0; k4 < 32; k4++) {
            float4 a = Xs[r * 32 + k4];
            float4 w = Wk[c * 32 + k4];
            acc += a.x * w.x + a.y * w.y + a.z * w.z + a.w * w.w;
        }
        out[(size_t)row * CC + c] = acc + __ldg(bias + c);
    }
}

// ---------------- host orchestration ----------------------------------------
extern "C" void kernel_launch(void* const* d_in, const int* in_sizes, int n_in,
                              void* d_out, int out_size) {
    const float* x  = (const float*)d_in[0];
    const int*   ei = (const int*)d_in[1];
    int E = in_sizes[1] / 2;
    const int* src = ei;
    const int* dst = ei + E;

    void* deg_p;
    cudaGetSymbolAddress(&deg_p, g_deg);

    const int SMEM_MMA   = 2 * STAGE_B;    // 81920
    const int SMEM_FINAL = (128 * 32 + CC * 32) * (int)sizeof(float4);
    cudaFuncSetAttribute(gemm_mma_kernel, cudaFuncAttributeMaxDynamicSharedMemorySize, SMEM_MMA);
    cudaFuncSetAttribute(final_kernel,    cudaFuncAttributeMaxDynamicSharedMemorySize, SMEM_FINAL);

    // ---- CSR build ----
    cudaMemsetAsync(deg_p, 0, NN * sizeof(int), 0);
    deg_kernel<<<(E + 255) / 256, 256>>>(dst, E);
    scan1_kernel<<<NBLK_SCAN, 1024>>>();
    scan2_kernel<<<1, 1>>>();
    scan3_kernel<<<(NN + 255) / 256, 256>>>();
    fill_kernel<<<(E + 255) / 256, 256>>>(src, dst, E);

    xconv_kernel<<<(NN * 32 + 255) / 256, 256>>>((const float4*)x);
    wconv_kernel<<<(3 * 2 * DD * DD + 255) / 256, 256>>>(
        (const float*)d_in[2],  (const float*)d_in[4],
        (const float*)d_in[7],  (const float*)d_in[9],
        (const float*)d_in[12], (const float*)d_in[14]);

    for (int L = 0; L < 3; L++) {
        const float* bg = (const float*)d_in[5 + 5 * L];
        const float* bb = (const float*)d_in[6 + 5 * L];

        gather_kernel<<<(NN * 32 + 255) / 256, 256>>>();
        gemm_mma_kernel<<<(NN + 127) / 128, 256, SMEM_MMA>>>(L);
        bnprep_kernel<<<1, DD>>>(bg, bb);
        bnfin_kernel<<<(NN * 16 + 255) / 256, 256>>>();
    }

    final_kernel<<<(NN + 127) / 128, 256, SMEM_FINAL>>>(
        (const float4*)d_in[17], (const float*)d_in[18], (float*)d_out);
}